// round 1
// baseline (speedup 1.0000x reference)
#include <cuda_runtime.h>
#include <cstdint>

#define EMB      128
#define NRAD     6
#define NDENSE   3
#define NT       12      // num targets
#define NTP      16      // padded targets in smem
#define MAX_ATOMS 20000

#define MLP_ROWS  68     // rows per MLP block
#define MLP_PAIRS 34     // row pairs per block
#define PH        35     // float2 pitch for h tile in smem (padded)

// -------- persistent device scratch (no allocations allowed) --------
__device__ float g_h[MAX_ATOMS * EMB];   // 10.24 MB scatter target, L2-resident
__device__ int   g_is64;                 // index dtype flag

typedef unsigned long long u64;

// -------- packed fp32x2 helpers (full-rate fp32 on Blackwell) --------
__device__ __forceinline__ u64 ffma2(u64 a, u64 b, u64 c) {
    u64 d;
    asm("fma.rn.f32x2 %0, %1, %2, %3;" : "=l"(d) : "l"(a), "l"(b), "l"(c));
    return d;
}
__device__ __forceinline__ u64 pack2(float x, float y) {
    u64 r;
    asm("mov.b64 %0, {%1, %2};" : "=l"(r) : "f"(x), "f"(y));
    return r;
}
__device__ __forceinline__ void unpack2(u64 v, float& x, float& y) {
    asm("mov.b64 {%0, %1}, %2;" : "=f"(x), "=f"(y) : "l"(v));
}
__device__ __forceinline__ float silu_f(float x) {
    return x / (1.0f + __expf(-x));
}

// ===================================================================
// Kernel 0: detect whether idnb_i is int64 or int32.
// If the buffer is int32, reading it as int64 merges adjacent indices:
// word = lo + (hi << 32) which is >= n_atoms unless hi == 0 (p ~ 1/20000).
// Scanning 4096 words makes misdetection probability ~0. Deterministic.
// ===================================================================
__global__ void detect_kernel(const void* __restrict__ idnb, int E, int n_atoms) {
    __shared__ int bad;
    if (threadIdx.x == 0) bad = 0;
    __syncthreads();
    const long long* p = (const long long*)idnb;
    int n = E / 2;                 // safe to read in both dtype cases
    if (n > 4096) n = 4096;
    for (int i = threadIdx.x; i < n; i += blockDim.x) {
        long long v = p[i];
        if (v < 0 || v >= (long long)n_atoms) bad = 1;
    }
    __syncthreads();
    if (threadIdx.x == 0) g_is64 = bad ? 0 : 1;
}

// ===================================================================
// Kernel 1: zero the scatter accumulator
// ===================================================================
__global__ void zero_kernel(int n4) {
    float4* h4 = (float4*)g_h;
    const float4 z = make_float4(0.f, 0.f, 0.f, 0.f);
    for (int i = blockIdx.x * blockDim.x + threadIdx.x; i < n4;
         i += gridDim.x * blockDim.x)
        h4[i] = z;
}

// ===================================================================
// Kernel 2: edge gate + scatter.
// One warp per edge: each lane owns 4 output columns (lane*4..+3).
// W_rbf columns for those lanes are loop-invariant -> preload into regs.
// Accumulate into g_h with vectorized red.global.add.v4.f32 (1 op / 16B).
// ===================================================================
__global__ void scatter_kernel(const float* __restrict__ x,
                               const float* __restrict__ rbf,
                               const void*  __restrict__ idnb,
                               const float* __restrict__ Wrbf,
                               int E) {
    const int lane = threadIdx.x & 31;
    int warp = (blockIdx.x * blockDim.x + threadIdx.x) >> 5;
    const int nwarps = (gridDim.x * blockDim.x) >> 5;

    // Preload W_rbf[r][lane*4 .. lane*4+3] for r=0..5 (24 regs)
    float4 w[NRAD];
    const float4* w4 = (const float4*)Wrbf;
#pragma unroll
    for (int r = 0; r < NRAD; ++r) w[r] = w4[r * 32 + lane];

    const bool is64 = (g_is64 != 0);
    const float4* x4 = (const float4*)x;
    const long long* i64 = (const long long*)idnb;
    const int* i32 = (const int*)idnb;

    for (int e = warp; e < E; e += nwarps) {
        const int idx = is64 ? (int)i64[e] : i32[e];
        const float* rb = rbf + (size_t)e * NRAD;
        const float r0 = rb[0], r1 = rb[1], r2 = rb[2];
        const float r3 = rb[3], r4 = rb[4], r5 = rb[5];

        const float4 xv = x4[(size_t)e * 32 + lane];

        float g0 = fmaf(r0, w[0].x, fmaf(r1, w[1].x, fmaf(r2, w[2].x,
                   fmaf(r3, w[3].x, fmaf(r4, w[4].x, r5 * w[5].x)))));
        float g1 = fmaf(r0, w[0].y, fmaf(r1, w[1].y, fmaf(r2, w[2].y,
                   fmaf(r3, w[3].y, fmaf(r4, w[4].y, r5 * w[5].y)))));
        float g2 = fmaf(r0, w[0].z, fmaf(r1, w[1].z, fmaf(r2, w[2].z,
                   fmaf(r3, w[3].z, fmaf(r4, w[4].z, r5 * w[5].z)))));
        float g3 = fmaf(r0, w[0].w, fmaf(r1, w[1].w, fmaf(r2, w[2].w,
                   fmaf(r3, w[3].w, fmaf(r4, w[4].w, r5 * w[5].w)))));

        const float v0 = g0 * xv.x, v1 = g1 * xv.y;
        const float v2 = g2 * xv.z, v3 = g3 * xv.w;

        float* dst = g_h + (size_t)idx * EMB + lane * 4;
        asm volatile("red.global.add.v4.f32 [%0], {%1, %2, %3, %4};"
                     :: "l"(dst), "f"(v0), "f"(v1), "f"(v2), "f"(v3)
                     : "memory");
    }
}

// ===================================================================
// Kernel 3: fused MLP head. Each block owns 68 atom rows (34 pairs),
// keeps them in SMEM as float2 pairs [col][pair], stages each layer's
// 128x128 weight in SMEM, computes with fma.rn.f32x2 (2 rows/op),
// then applies the final 128x12 projection directly to d_out.
// 295 blocks, 2 blocks/SM -> one balanced wave on 148 SMs.
// ===================================================================
#define HS_BYTES   (EMB * PH * 8)          // 35840
#define WS_OFF     HS_BYTES
#define WS_BYTES   (EMB * EMB * 4)         // 65536
#define WFS_OFF    (WS_OFF + WS_BYTES)
#define WFS_BYTES  (EMB * NTP * 4)         // 8192
#define BS_OFF     (WFS_OFF + WFS_BYTES)
#define BS_BYTES   (EMB * 4)               // 512
#define SMEM_TOTAL (BS_OFF + BS_BYTES)     // 110080

__global__ __launch_bounds__(256, 2)
void mlp_kernel(const float* __restrict__ dW, const float* __restrict__ dB,
                const float* __restrict__ Wf, float* __restrict__ out,
                int n_atoms) {
    extern __shared__ char smem[];
    u64*   hsu = (u64*)smem;                       // [col][pair], pitch PH
    float* hsf = (float*)smem;                     // float view, pitch 2*PH
    float* Ws  = (float*)(smem + WS_OFF);          // layer weight [k][j]
    float* Wfs = (float*)(smem + WFS_OFF);         // final weight [k][c] padded 16
    float* bss = (float*)(smem + BS_OFF);          // bias

    const int t = threadIdx.x;
    const int rowbase = blockIdx.x * MLP_ROWS;

    // ---- load h tile (coalesced global, transpose into [col][row]) ----
    for (int idx = t; idx < MLP_ROWS * EMB; idx += 256) {
        const int r = idx >> 7, c = idx & 127;
        const int gr = rowbase + r;
        const float v = (gr < n_atoms) ? g_h[(size_t)gr * EMB + c] : 0.f;
        hsf[c * (2 * PH) + r] = v;
    }
    // ---- load final weight (padded to 16 cols) ----
    if (t < EMB) {
#pragma unroll
        for (int c = 0; c < NT; ++c) Wfs[t * NTP + c] = Wf[t * NT + c];
    }

    const int j0 = (t & 31) * 4;   // 4 output columns per thread
    const int pg = t >> 5;         // pair group 0..7

    // ---- dense layers ----
    for (int li = 0; li < NDENSE; ++li) {
        const float* W = dW + (size_t)li * EMB * EMB;
        for (int idx = t; idx < EMB * EMB; idx += 256) Ws[idx] = W[idx];
        if (t < EMB) bss[t] = dB[li * EMB + t];
        __syncthreads();

        u64 acc[5][4];
#pragma unroll
        for (int p = 0; p < 5; ++p)
#pragma unroll
            for (int q = 0; q < 4; ++q) acc[p][q] = 0ull;

#pragma unroll 4
        for (int k = 0; k < EMB; ++k) {
            const float4 wv = *(const float4*)&Ws[k * EMB + j0];
            const u64 w0 = pack2(wv.x, wv.x);
            const u64 w1 = pack2(wv.y, wv.y);
            const u64 w2 = pack2(wv.z, wv.z);
            const u64 w3 = pack2(wv.w, wv.w);
            const u64* hrow = hsu + k * PH;
#pragma unroll
            for (int p = 0; p < 4; ++p) {
                const u64 hv = hrow[pg + p * 8];
                acc[p][0] = ffma2(hv, w0, acc[p][0]);
                acc[p][1] = ffma2(hv, w1, acc[p][1]);
                acc[p][2] = ffma2(hv, w2, acc[p][2]);
                acc[p][3] = ffma2(hv, w3, acc[p][3]);
            }
            if (pg < 2) {   // tail pairs 32,33 (uniform branch per warp)
                const u64 hv = hrow[pg + 32];
                acc[4][0] = ffma2(hv, w0, acc[4][0]);
                acc[4][1] = ffma2(hv, w1, acc[4][1]);
                acc[4][2] = ffma2(hv, w2, acc[4][2]);
                acc[4][3] = ffma2(hv, w3, acc[4][3]);
            }
        }

        float b[4];
#pragma unroll
        for (int q = 0; q < 4; ++q) b[q] = bss[j0 + q];

        __syncthreads();   // all reads of hs done -> safe to overwrite

#pragma unroll
        for (int p = 0; p < 5; ++p) {
            if (p == 4 && pg >= 2) break;
            const int pr = pg + p * 8;
#pragma unroll
            for (int q = 0; q < 4; ++q) {
                float lo, hi;
                unpack2(acc[p][q], lo, hi);
                lo = silu_f(lo + b[q]);
                hi = silu_f(hi + b[q]);
                hsu[(j0 + q) * PH + pr] = pack2(lo, hi);
            }
        }
        __syncthreads();
    }

    // ---- final projection: [68,128] @ [128,12] -> out ----
    const int c = t & 15;
    const int grp = t >> 4;      // 0..15
    if (c < NT) {
#pragma unroll
        for (int i = 0; i < 3; ++i) {
            const int pr = grp + 16 * i;
            if (pr < MLP_PAIRS) {
                u64 acc = 0ull;
#pragma unroll 4
                for (int k = 0; k < EMB; ++k) {
                    const float wfv = Wfs[k * NTP + c];
                    acc = ffma2(hsu[k * PH + pr], pack2(wfv, wfv), acc);
                }
                float lo, hi;
                unpack2(acc, lo, hi);
                const int r0 = rowbase + 2 * pr;
                if (r0 < n_atoms)     out[(size_t)r0 * NT + c]       = lo;
                if (r0 + 1 < n_atoms) out[(size_t)(r0 + 1) * NT + c] = hi;
            }
        }
    }
}

// ===================================================================
extern "C" void kernel_launch(void* const* d_in, const int* in_sizes, int n_in,
                              void* d_out, int out_size) {
    const float* x    = (const float*)d_in[0];
    const float* rbf  = (const float*)d_in[1];
    const void*  idnb =               d_in[2];
    // d_in[3] = n_atoms scalar (derive from out_size instead)
    const float* Wrbf = (const float*)d_in[4];
    const float* dW   = (const float*)d_in[5];
    const float* dB   = (const float*)d_in[6];
    const float* Wf   = (const float*)d_in[7];
    float* out = (float*)d_out;

    const int E = in_sizes[0] / EMB;
    const int n_atoms = out_size / NT;

    detect_kernel<<<1, 256>>>(idnb, E, n_atoms);
    zero_kernel<<<512, 256>>>(n_atoms * (EMB / 4));
    scatter_kernel<<<1184, 256>>>(x, rbf, idnb, Wrbf, E);

    cudaFuncSetAttribute(mlp_kernel, cudaFuncAttributeMaxDynamicSharedMemorySize,
                         SMEM_TOTAL);
    const int blocks = (n_atoms + MLP_ROWS - 1) / MLP_ROWS;
    mlp_kernel<<<blocks, 256, SMEM_TOTAL>>>(dW, dB, Wf, out, n_atoms);
}